// round 11
// baseline (speedup 1.0000x reference)
#include <cuda_runtime.h>
#include <math.h>

#define BB 8
#define NN 8192
#define SS 2048
#define KK 32
#define CNT (BB*SS*KK)          // 524288 elements per layer
#define OUT_XYZ_ELEMS (BB*SS*3) // 49152

typedef unsigned long long ull;

// ---------------- scratch (static device memory; no runtime allocation) ----
__device__ float g_bufA[(size_t)CNT * 32];  // 64 MB : z1 (32ch), channel-major [c][e]
__device__ float g_bufB[(size_t)CNT * 32];  // 64 MB : z2 (32ch), channel-major
__device__ float g_max[(size_t)BB * SS * 64]; // 4 MB : per-(b,s) max_k z3, [bs][o]
__device__ int   g_fps[BB * SS];
__device__ int   g_ball[BB * SS * KK];
__device__ float g_stats[3 * 128];          // per layer: [0..63]=sum, [64..127]=sumsq

// ---------------- packed f32x2 helpers (sm_103a) ---------------------------
__device__ __forceinline__ ull pack2(float lo, float hi) {
    ull r; asm("mov.b64 %0,{%1,%2};" : "=l"(r) : "f"(lo), "f"(hi)); return r;
}
__device__ __forceinline__ void unpack2(ull v, float& lo, float& hi) {
    asm("mov.b64 {%0,%1},%2;" : "=f"(lo), "=f"(hi) : "l"(v));
}
__device__ __forceinline__ ull add2(ull a, ull b) {
    ull r; asm("add.rn.f32x2 %0,%1,%2;" : "=l"(r) : "l"(a), "l"(b)); return r;
}
__device__ __forceinline__ ull mul2(ull a, ull b) {
    ull r; asm("mul.rn.f32x2 %0,%1,%2;" : "=l"(r) : "l"(a), "l"(b)); return r;
}
__device__ __forceinline__ ull fma2(ull a, ull b, ull c) {
    ull r; asm("fma.rn.f32x2 %0,%1,%2,%3;" : "=l"(r) : "l"(a), "l"(b), "l"(c)); return r;
}

// ============================================================================
// 1) Farthest point sampling. One block per batch, 512 threads x 16 points in
//    registers. Inner loop: validated bit-exact (p-c)^2 packed form. Tail is
//    SINGLE-BARRIER: every warp rescans for its min winning index (issue work,
//    overlapped across warps), lane0 stores the 64-bit key (dist_bits<<32 |
//    NN-1-idx) to double-buffered skey; after ONE barrier each warp does one
//    LDS.64 + two 32-bit REDUXes to find the block winner. Bit-identical
//    selection: max dist, then min index (max of the complemented low field).
// ============================================================================
__global__ void __launch_bounds__(512) fps_kernel(const float* __restrict__ xyz)
{
    const int b = blockIdx.x;
    const float* base = xyz + (size_t)b * NN * 3;
    const int t = threadIdx.x;
    const int lane = t & 31, wid = t >> 5;

    // 16 points per thread: dd[j] <-> point index t + j*512
    ull px[8], py[8], pz[8];
    float dd[16];
#pragma unroll
    for (int k = 0; k < 8; k++) {
        const int p0 = t + (2 * k) * 512;
        const int p1 = t + (2 * k + 1) * 512;
        px[k] = pack2(base[3 * p0 + 0], base[3 * p1 + 0]);
        py[k] = pack2(base[3 * p0 + 1], base[3 * p1 + 1]);
        pz[k] = pack2(base[3 * p0 + 2], base[3 * p1 + 2]);
    }
#pragma unroll
    for (int j = 0; j < 16; j++) dd[j] = 1e10f;

    __shared__ ull skey[2][16];     // double-buffered per-warp keys (no reset:
                                    // every warp writes its slot every iter)

    float cx = base[0], cy = base[1], cz = base[2];
    int cur = 0;

    for (int it = 0; it < SS; it++) {
        if (t == 0) g_fps[b * SS + it] = cur;

        const ull ncx = pack2(-cx, -cx);
        const ull ncy = pack2(-cy, -cy);
        const ull ncz = pack2(-cz, -cz);

        float m = 0.f;                      // dists >= 0, so 0 is a safe identity
#pragma unroll
        for (int k = 0; k < 8; k++) {
            ull dx = add2(px[k], ncx);
            ull dy = add2(py[k], ncy);
            ull dz = add2(pz[k], ncz);
            ull d2 = mul2(dx, dx);
            d2 = fma2(dy, dy, d2);
            d2 = fma2(dz, dz, d2);
            float dlo, dhi; unpack2(d2, dlo, dhi);
            const float nlo = fminf(dd[2 * k],     dlo);
            const float nhi = fminf(dd[2 * k + 1], dhi);
            dd[2 * k]     = nlo;
            dd[2 * k + 1] = nhi;
            m = fmaxf(m, fmaxf(nlo, nhi));
        }
        // warp max on float bits (all values >= 0 -> unsigned order == float order)
        const unsigned mb   = __float_as_uint(m);
        const unsigned wmax = __reduce_max_sync(0xffffffffu, mb);
        // every warp finds its min winning index (overlapped issue work)
        unsigned bi = 0xffffffffu;
        if (mb == wmax) {                   // usually 1 lane per warp
#pragma unroll
            for (int j = 15; j >= 0; j--)   // descending -> smallest index wins
                if (__float_as_uint(dd[j]) == wmax) bi = (unsigned)(t + j * 512);
        }
        const unsigned rid = __reduce_min_sync(0xffffffffu, bi);
        if (lane == 0)
            skey[it & 1][wid] = ((ull)wmax << 32)
                              | (ull)(unsigned)(NN - 1 - (int)rid);
        __syncthreads();                    // the ONLY barrier per iteration

        // block winner via one LDS.64 + two chained 32-bit REDUXes
        const ull kk = skey[it & 1][lane & 15];
        const unsigned hi = (unsigned)(kk >> 32);
        const unsigned lo = (unsigned)kk;
        const unsigned bmax = __reduce_max_sync(0xffffffffu, hi);
        const unsigned sel  = (hi == bmax) ? lo : 0u;   // lo = NN-1-idx
        const unsigned rmax = __reduce_max_sync(0xffffffffu, sel);
        cur = NN - 1 - (int)rmax;

        cx = base[3 * cur + 0];   // broadcast L1 hit
        cy = base[3 * cur + 1];
        cz = base[3 * cur + 2];
    }
}

// ============================================================================
// 2) new_xyz gather + ball query, smem-tiled. Block = 8 warps = 8 centroids,
//    all in the same batch. Block 0 also zeroes g_stats (all 384, strided).
// ============================================================================
#define TPTS 1024
__global__ void __launch_bounds__(256) bq_kernel(const float* __restrict__ xyz,
                                                 float* __restrict__ newxyz)
{
    const int tid = threadIdx.x;
    if (blockIdx.x == 0) {
        for (int i = tid; i < 384; i += 256) g_stats[i] = 0.f;
    }

    const int warp = tid >> 5, lane = tid & 31;
    const int gs = blockIdx.x * 8 + warp;          // 0 .. 16383
    const int b  = gs >> 11;                        // same for whole block
    const float* base = xyz + (size_t)b * NN * 3;

    __shared__ float spts[TPTS * 3];
    __shared__ int   sidx[8][KK];
    __shared__ int   sdone;
    if (tid == 0) sdone = 0;

    const int ci = g_fps[gs];
    const float cx = base[3 * ci + 0];
    const float cy = base[3 * ci + 1];
    const float cz = base[3 * ci + 2];
    if (lane < 3) newxyz[(size_t)gs * 3 + lane] = base[3 * ci + lane];

    const float r2 = (float)(0.2 * 0.2);
    int cnt = 0, first = 0x7fffffff;
    bool done = false;

    for (int tile = 0; tile < NN; tile += TPTS) {
        __syncthreads();
        if (sdone == 8) break;
        for (int i = tid; i < TPTS * 3; i += 256)
            spts[i] = base[(size_t)tile * 3 + i];
        __syncthreads();

        if (!done) {
            for (int p0 = 0; p0 < TPTS; p0 += 32) {
                const int p = p0 + lane;
                float dx = spts[3 * p + 0] - cx;
                float dy = spts[3 * p + 1] - cy;
                float dz = spts[3 * p + 2] - cz;
                float sq = dx * dx + dy * dy + dz * dz;
                bool  in = !(sq > r2);
                unsigned mm = __ballot_sync(0xffffffffu, in);
                if (in) {
                    int pos = cnt + __popc(mm & ((1u << lane) - 1u));
                    if (pos < KK) sidx[warp][pos] = tile + p;
                    if (pos == 0) first = tile + p;
                }
                cnt += __popc(mm);
                if (cnt >= KK) break;
            }
            if (cnt >= KK) {
                done = true;
                if (lane == 0) atomicAdd(&sdone, 1);
            }
        }
    }
#pragma unroll
    for (int off = 16; off > 0; off >>= 1)
        first = min(first, __shfl_down_sync(0xffffffffu, first, off));
    first = __shfl_sync(0xffffffffu, first, 0);

    const int cc = cnt < KK ? cnt : KK;
    const int v  = (lane < cc) ? sidx[warp][lane] : first;
    g_ball[(size_t)gs * KK + lane] = v;
}

// ============================================================================
// stats: warp reduce (sum, sumsq) then shared atomics
// ============================================================================
__device__ __forceinline__ void warp_stat_accum2(float v, float v2, int c, int lane,
                                                 float* ssum, float* ssq)
{
#pragma unroll
    for (int off = 16; off > 0; off >>= 1) {
        v  += __shfl_down_sync(0xffffffffu, v,  off);
        v2 += __shfl_down_sync(0xffffffffu, v2, off);
    }
    if (lane == 0) { atomicAdd(&ssum[c], v); atomicAdd(&ssq[c], v2); }
}

// BN affine from stats (same math as the old fin_kernel, computed inline)
__device__ __forceinline__ void bn_affine(int L, int c,
                                          const float* __restrict__ g,
                                          const float* __restrict__ be,
                                          float& a, float& cc)
{
    const float inv  = 1.f / (float)CNT;
    const float mean = g_stats[L * 128 + c] * inv;
    const float var  = g_stats[L * 128 + 64 + c] * inv - mean * mean;
    a  = g[c] * rsqrtf(var + 1e-5f);
    cc = be[c] - mean * a;
}

// ============================================================================
// 3) Layer 1: gather features (2 elements/thread), packed 6->32 conv, z1, stats.
// ============================================================================
__global__ void __launch_bounds__(256) l1_kernel(const float* __restrict__ xyz,
                                                 const float* __restrict__ pts,
                                                 const float* __restrict__ w,
                                                 const float* __restrict__ bias,
                                                 const float* __restrict__ newxyz)
{
    __shared__ ull   swd[192];
    __shared__ ull   sb2[32];
    __shared__ float ssum[32], ssq[32];
    const int tid = threadIdx.x, lane = tid & 31;
    if (tid < 192) { float v = w[tid]; swd[tid] = pack2(v, v); }
    if (tid < 32)  { float v = bias[tid]; sb2[tid] = pack2(v, v); ssum[tid] = 0.f; ssq[tid] = 0.f; }
    __syncthreads();

    const int gt = blockIdx.x * 256 + tid;        // pair id < CNT/2
    const int e0 = 2 * gt;
    const int bs = e0 >> 5;
    const int b  = bs >> 11;
    const int2 pp = *(const int2*)&g_ball[e0];
    const float* xb = xyz + (size_t)b * NN * 3;
    const float* pb = pts + (size_t)b * NN * 3;
    const float nx = newxyz[(size_t)bs * 3 + 0];
    const float ny = newxyz[(size_t)bs * 3 + 1];
    const float nz = newxyz[(size_t)bs * 3 + 2];

    ull in2[6];
    in2[0] = pack2(xb[3 * pp.x + 0] - nx, xb[3 * pp.y + 0] - nx);
    in2[1] = pack2(xb[3 * pp.x + 1] - ny, xb[3 * pp.y + 1] - ny);
    in2[2] = pack2(xb[3 * pp.x + 2] - nz, xb[3 * pp.y + 2] - nz);
    in2[3] = pack2(pb[3 * pp.x + 0], pb[3 * pp.y + 0]);
    in2[4] = pack2(pb[3 * pp.x + 1], pb[3 * pp.y + 1]);
    in2[5] = pack2(pb[3 * pp.x + 2], pb[3 * pp.y + 2]);

#pragma unroll 4
    for (int o = 0; o < 32; o++) {
        ull acc = sb2[o];
#pragma unroll
        for (int i = 0; i < 6; i++) acc = fma2(swd[o * 6 + i], in2[i], acc);
        *(ull*)&g_bufA[(size_t)o * CNT + e0] = acc;     // STG.64, coalesced
        float lo, hi; unpack2(acc, lo, hi);
        warp_stat_accum2(lo + hi, fmaf(hi, hi, lo * lo), o, lane, ssum, ssq);
    }
    __syncthreads();
    if (tid < 32) {
        atomicAdd(&g_stats[0 * 128 + tid],      ssum[tid]);
        atomicAdd(&g_stats[0 * 128 + 64 + tid], ssq[tid]);
    }
}

// ============================================================================
// 4) Layer 2: BN1+relu on z1 (affine computed inline from stats), packed
//    32->32 conv (2 elements/thread), z2, stats.
// ============================================================================
__global__ void __launch_bounds__(256) l2_kernel(const float* __restrict__ w,
                                                 const float* __restrict__ bias,
                                                 const float* __restrict__ g0,
                                                 const float* __restrict__ be0)
{
    __shared__ ull   swd[1024];
    __shared__ ull   sb2[32], sa2[32], sc2[32];
    __shared__ float ssum[32], ssq[32];
    const int tid = threadIdx.x, lane = tid & 31;
    for (int i = tid; i < 1024; i += 256) { float v = w[i]; swd[i] = pack2(v, v); }
    if (tid < 32) {
        float v = bias[tid]; sb2[tid] = pack2(v, v);
        float a, c; bn_affine(0, tid, g0, be0, a, c);
        sa2[tid] = pack2(a, a); sc2[tid] = pack2(c, c);
        ssum[tid] = 0.f; ssq[tid] = 0.f;
    }
    __syncthreads();

    const int e0 = 2 * (blockIdx.x * 256 + tid);
    ull h2[32];
#pragma unroll
    for (int i = 0; i < 32; i++) {
        ull z = *(const ull*)&g_bufA[(size_t)i * CNT + e0];
        ull t = fma2(sa2[i], z, sc2[i]);
        float lo, hi; unpack2(t, lo, hi);
        h2[i] = pack2(fmaxf(lo, 0.f), fmaxf(hi, 0.f));
    }
#pragma unroll 2
    for (int o = 0; o < 32; o++) {
        ull acc = sb2[o];
#pragma unroll
        for (int i = 0; i < 32; i++) acc = fma2(swd[o * 32 + i], h2[i], acc);
        *(ull*)&g_bufB[(size_t)o * CNT + e0] = acc;
        float lo, hi; unpack2(acc, lo, hi);
        warp_stat_accum2(lo + hi, fmaf(hi, hi, lo * lo), o, lane, ssum, ssq);
    }
    __syncthreads();
    if (tid < 32) {
        atomicAdd(&g_stats[1 * 128 + tid],      ssum[tid]);
        atomicAdd(&g_stats[1 * 128 + 64 + tid], ssq[tid]);
    }
}

// ============================================================================
// 5) Layer 3: BN2+relu on z2 (affine inline), packed 32->64 conv, stats, and
//    FUSED max over k: z3 never hits DRAM (bit-exact: a3>0, monotone fmaf/relu).
// ============================================================================
__global__ void __launch_bounds__(256) l3_kernel(const float* __restrict__ w,
                                                 const float* __restrict__ bias,
                                                 const float* __restrict__ g1,
                                                 const float* __restrict__ be1)
{
    __shared__ ull   swd[2048];       // 16KB
    __shared__ ull   sb2[64], sa2[32], sc2[32];
    __shared__ float ssum[64], ssq[64];
    __shared__ float smax[16][64];    // 16 bs-groups per block
    const int tid = threadIdx.x, lane = tid & 31, warp = tid >> 5;
    for (int i = tid; i < 2048; i += 256) { float v = w[i]; swd[i] = pack2(v, v); }
    if (tid < 64) { float v = bias[tid]; sb2[tid] = pack2(v, v); ssum[tid] = 0.f; ssq[tid] = 0.f; }
    if (tid < 32) {
        float a, c; bn_affine(1, tid, g1, be1, a, c);
        sa2[tid] = pack2(a, a); sc2[tid] = pack2(c, c);
    }
    __syncthreads();

    const int e0 = 2 * (blockIdx.x * 256 + tid);
    ull h2[32];
#pragma unroll
    for (int i = 0; i < 32; i++) {
        ull z = *(const ull*)&g_bufB[(size_t)i * CNT + e0];
        ull t = fma2(sa2[i], z, sc2[i]);
        float lo, hi; unpack2(t, lo, hi);
        h2[i] = pack2(fmaxf(lo, 0.f), fmaxf(hi, 0.f));
    }
    const int seg = (warp << 1) + (lane >> 4);    // bs-group within block (0..15)
#pragma unroll 1
    for (int o = 0; o < 64; o++) {
        ull acc = sb2[o];
#pragma unroll
        for (int i = 0; i < 32; i++) acc = fma2(swd[o * 32 + i], h2[i], acc);
        float lo, hi; unpack2(acc, lo, hi);
        float mx = fmaxf(lo, hi);
#pragma unroll
        for (int off = 8; off > 0; off >>= 1)
            mx = fmaxf(mx, __shfl_down_sync(0xffffffffu, mx, off, 16));
        if ((lane & 15) == 0) smax[seg][o] = mx;
        warp_stat_accum2(lo + hi, fmaf(hi, hi, lo * lo), o, lane, ssum, ssq);
    }
    __syncthreads();
    {
        const int bs0 = blockIdx.x * 16;
        for (int i = tid; i < 16 * 64; i += 256)
            g_max[(size_t)bs0 * 64 + i] = smax[i >> 6][i & 63];
    }
    if (tid < 64) {
        atomicAdd(&g_stats[2 * 128 + tid],      ssum[tid]);
        atomicAdd(&g_stats[2 * 128 + 64 + tid], ssq[tid]);
    }
}

// ============================================================================
// 6) Finalize: BN3 affine (inline from stats) + relu on the per-(bs,o) maxima.
// ============================================================================
__global__ void __launch_bounds__(256) final_kernel(const float* __restrict__ g2,
                                                    const float* __restrict__ be2,
                                                    float* __restrict__ out)
{
    __shared__ float sa[64], sc[64];
    const int tid = threadIdx.x;
    if (tid < 64) {
        float a, c; bn_affine(2, tid, g2, be2, a, c);
        sa[tid] = a; sc[tid] = c;
    }
    __syncthreads();

    const int idx = blockIdx.x * 256 + tid;       // < BB*SS*64
    const int o = idx & 63;
    const float v = g_max[idx];
    out[OUT_XYZ_ELEMS + idx] = fmaxf(fmaf(sa[o], v, sc[o]), 0.f);
}

// ============================================================================
extern "C" void kernel_launch(void* const* d_in, const int* in_sizes, int n_in,
                              void* d_out, int out_size)
{
    const float* xyz = (const float*)d_in[0];
    const float* pts = (const float*)d_in[1];
    const float* w0  = (const float*)d_in[2];
    const float* b0  = (const float*)d_in[3];
    const float* g0  = (const float*)d_in[4];
    const float* be0 = (const float*)d_in[5];
    const float* w1  = (const float*)d_in[6];
    const float* b1  = (const float*)d_in[7];
    const float* g1  = (const float*)d_in[8];
    const float* be1 = (const float*)d_in[9];
    const float* w2  = (const float*)d_in[10];
    const float* b2  = (const float*)d_in[11];
    const float* g2  = (const float*)d_in[12];
    const float* be2 = (const float*)d_in[13];
    float* out = (float*)d_out;

    fps_kernel<<<BB, 512>>>(xyz);
    bq_kernel<<<(BB * SS) / 8, 256>>>(xyz, out);
    l1_kernel<<<CNT / 512, 256>>>(xyz, pts, w0, b0, out);
    l2_kernel<<<CNT / 512, 256>>>(w1, b1, g0, be0);
    l3_kernel<<<CNT / 512, 256>>>(w2, b2, g1, be1);
    final_kernel<<<(BB * SS * 64) / 256, 256>>>(g2, be2, out);
}

// round 12
// speedup vs baseline: 1.0656x; 1.0656x over previous
#include <cuda_runtime.h>
#include <math.h>

#define BB 8
#define NN 8192
#define SS 2048
#define KK 32
#define CNT (BB*SS*KK)          // 524288 elements per layer
#define OUT_XYZ_ELEMS (BB*SS*3) // 49152

typedef unsigned long long ull;

// ---------------- scratch (static device memory; no runtime allocation) ----
__device__ float g_bufA[(size_t)CNT * 32];  // 64 MB : z1 (32ch), channel-major [c][e]
__device__ float g_bufB[(size_t)CNT * 32];  // 64 MB : z2 (32ch), channel-major
__device__ float g_max[(size_t)BB * SS * 64]; // 4 MB : per-(b,s) max_k z3, [bs][o]
__device__ int   g_fps[BB * SS];
__device__ int   g_ball[BB * SS * KK];
__device__ float g_stats[3 * 128];          // per layer: [0..63]=sum, [64..127]=sumsq

// ---------------- packed f32x2 helpers (sm_103a) ---------------------------
__device__ __forceinline__ ull pack2(float lo, float hi) {
    ull r; asm("mov.b64 %0,{%1,%2};" : "=l"(r) : "f"(lo), "f"(hi)); return r;
}
__device__ __forceinline__ void unpack2(ull v, float& lo, float& hi) {
    asm("mov.b64 {%0,%1},%2;" : "=f"(lo), "=f"(hi) : "l"(v));
}
__device__ __forceinline__ ull add2(ull a, ull b) {
    ull r; asm("add.rn.f32x2 %0,%1,%2;" : "=l"(r) : "l"(a), "l"(b)); return r;
}
__device__ __forceinline__ ull mul2(ull a, ull b) {
    ull r; asm("mul.rn.f32x2 %0,%1,%2;" : "=l"(r) : "l"(a), "l"(b)); return r;
}
__device__ __forceinline__ ull fma2(ull a, ull b, ull c) {
    ull r; asm("fma.rn.f32x2 %0,%1,%2,%3;" : "=l"(r) : "l"(a), "l"(b), "l"(c)); return r;
}

// ============================================================================
// 1) Farthest point sampling. One block per batch, 512 threads x 16 points in
//    registers. Inner loop: validated bit-exact (p-c)^2 packed form with two
//    independent running-max accumulators (breaks the serial fmax chain; max
//    is exact so the result is bit-identical). Tail (round-10 structure):
//      - lane0 stores warp max DIST BITS to sdist[wid]; bar1
//      - ONE REDUX over sdist[lane&15] -> block max bmax
//      - ONLY warps with wmax==bmax rescan for the smallest local index,
//        REDUX min, lane0 atomicMin into a 3-slot rotating shared inbox
//      - bar2; everyone reads winner index, loads coords (L1 hit)
//    Selection bit-identical: same max, same min-index tie-break.
// ============================================================================
__global__ void __launch_bounds__(512) fps_kernel(const float* __restrict__ xyz)
{
    const int b = blockIdx.x;
    const float* base = xyz + (size_t)b * NN * 3;
    const int t = threadIdx.x;
    const int lane = t & 31, wid = t >> 5;

    // 16 points per thread: dd[j] <-> point index t + j*512
    ull px[8], py[8], pz[8];
    float dd[16];
#pragma unroll
    for (int k = 0; k < 8; k++) {
        const int p0 = t + (2 * k) * 512;
        const int p1 = t + (2 * k + 1) * 512;
        px[k] = pack2(base[3 * p0 + 0], base[3 * p1 + 0]);
        py[k] = pack2(base[3 * p0 + 1], base[3 * p1 + 1]);
        pz[k] = pack2(base[3 * p0 + 2], base[3 * p1 + 2]);
    }
#pragma unroll
    for (int j = 0; j < 16; j++) dd[j] = 1e10f;

    __shared__ unsigned sdist[16];   // per-warp max dist bits (bar1/bar2 sandwich)
    __shared__ unsigned sidxs[3];    // 3-slot rotating winner-index inbox
    if (t < 3) sidxs[t] = 0xffffffffu;
    __syncthreads();

    float cx = base[0], cy = base[1], cz = base[2];
    int cur = 0;
    int slot = 0, nslot = 1, rslot = 2;

    for (int it = 0; it < SS; it++) {
        if (t == 0) {
            g_fps[b * SS + it] = cur;
            sidxs[nslot] = 0xffffffffu;     // reset next slot (barrier-ordered)
        }
        const ull ncx = pack2(-cx, -cx);
        const ull ncy = pack2(-cy, -cy);
        const ull ncz = pack2(-cz, -cz);

        float m0 = 0.f, m1 = 0.f;           // dists >= 0: two independent chains
#pragma unroll
        for (int k = 0; k < 8; k++) {
            ull dx = add2(px[k], ncx);
            ull dy = add2(py[k], ncy);
            ull dz = add2(pz[k], ncz);
            ull d2 = mul2(dx, dx);
            d2 = fma2(dy, dy, d2);
            d2 = fma2(dz, dz, d2);
            float dlo, dhi; unpack2(d2, dlo, dhi);
            const float nlo = fminf(dd[2 * k],     dlo);
            const float nhi = fminf(dd[2 * k + 1], dhi);
            dd[2 * k]     = nlo;
            dd[2 * k + 1] = nhi;
            m0 = fmaxf(m0, nlo);
            m1 = fmaxf(m1, nhi);
        }
        const float m = fmaxf(m0, m1);
        // warp max on float bits (all values >= 0 -> unsigned order == float order)
        const unsigned mb   = __float_as_uint(m);
        const unsigned wmax = __reduce_max_sync(0xffffffffu, mb);
        if (lane == 0) sdist[wid] = wmax;
        __syncthreads();                    // bar1

        // block max via ONE warp-REDUX over the 16 per-warp maxima
        const unsigned bmax = __reduce_max_sync(0xffffffffu, sdist[lane & 15]);

        if (wmax == bmax) {                 // warp-uniform: ~1 warp enters
            unsigned bi = 0xffffffffu;
            if (mb == bmax) {               // usually 1 lane
#pragma unroll
                for (int j = 15; j >= 0; j--)
                    if (__float_as_uint(dd[j]) == bmax) bi = (unsigned)(t + j * 512);
            }
            const unsigned rid = __reduce_min_sync(0xffffffffu, bi);
            if (lane == 0) atomicMin(&sidxs[slot], rid);
        }
        __syncthreads();                    // bar2

        cur = (int)sidxs[slot];
        cx = base[3 * cur + 0];   // broadcast L1 hit
        cy = base[3 * cur + 1];
        cz = base[3 * cur + 2];

        const int tmp = slot; slot = nslot; nslot = rslot; rslot = tmp;
    }
}

// ============================================================================
// 2) new_xyz gather + ball query, smem-tiled. Block = 8 warps = 8 centroids,
//    all in the same batch. Block 0 also zeroes g_stats (all 384, strided).
// ============================================================================
#define TPTS 1024
__global__ void __launch_bounds__(256) bq_kernel(const float* __restrict__ xyz,
                                                 float* __restrict__ newxyz)
{
    const int tid = threadIdx.x;
    if (blockIdx.x == 0) {
        for (int i = tid; i < 384; i += 256) g_stats[i] = 0.f;
    }

    const int warp = tid >> 5, lane = tid & 31;
    const int gs = blockIdx.x * 8 + warp;          // 0 .. 16383
    const int b  = gs >> 11;                        // same for whole block
    const float* base = xyz + (size_t)b * NN * 3;

    __shared__ float spts[TPTS * 3];
    __shared__ int   sidx[8][KK];
    __shared__ int   sdone;
    if (tid == 0) sdone = 0;

    const int ci = g_fps[gs];
    const float cx = base[3 * ci + 0];
    const float cy = base[3 * ci + 1];
    const float cz = base[3 * ci + 2];
    if (lane < 3) newxyz[(size_t)gs * 3 + lane] = base[3 * ci + lane];

    const float r2 = (float)(0.2 * 0.2);
    int cnt = 0, first = 0x7fffffff;
    bool done = false;

    for (int tile = 0; tile < NN; tile += TPTS) {
        __syncthreads();
        if (sdone == 8) break;
        for (int i = tid; i < TPTS * 3; i += 256)
            spts[i] = base[(size_t)tile * 3 + i];
        __syncthreads();

        if (!done) {
            for (int p0 = 0; p0 < TPTS; p0 += 32) {
                const int p = p0 + lane;
                float dx = spts[3 * p + 0] - cx;
                float dy = spts[3 * p + 1] - cy;
                float dz = spts[3 * p + 2] - cz;
                float sq = dx * dx + dy * dy + dz * dz;
                bool  in = !(sq > r2);
                unsigned mm = __ballot_sync(0xffffffffu, in);
                if (in) {
                    int pos = cnt + __popc(mm & ((1u << lane) - 1u));
                    if (pos < KK) sidx[warp][pos] = tile + p;
                    if (pos == 0) first = tile + p;
                }
                cnt += __popc(mm);
                if (cnt >= KK) break;
            }
            if (cnt >= KK) {
                done = true;
                if (lane == 0) atomicAdd(&sdone, 1);
            }
        }
    }
#pragma unroll
    for (int off = 16; off > 0; off >>= 1)
        first = min(first, __shfl_down_sync(0xffffffffu, first, off));
    first = __shfl_sync(0xffffffffu, first, 0);

    const int cc = cnt < KK ? cnt : KK;
    const int v  = (lane < cc) ? sidx[warp][lane] : first;
    g_ball[(size_t)gs * KK + lane] = v;
}

// ============================================================================
// stats: warp reduce (sum, sumsq) then shared atomics
// ============================================================================
__device__ __forceinline__ void warp_stat_accum2(float v, float v2, int c, int lane,
                                                 float* ssum, float* ssq)
{
#pragma unroll
    for (int off = 16; off > 0; off >>= 1) {
        v  += __shfl_down_sync(0xffffffffu, v,  off);
        v2 += __shfl_down_sync(0xffffffffu, v2, off);
    }
    if (lane == 0) { atomicAdd(&ssum[c], v); atomicAdd(&ssq[c], v2); }
}

// BN affine from stats (same math as the old fin_kernel, computed inline)
__device__ __forceinline__ void bn_affine(int L, int c,
                                          const float* __restrict__ g,
                                          const float* __restrict__ be,
                                          float& a, float& cc)
{
    const float inv  = 1.f / (float)CNT;
    const float mean = g_stats[L * 128 + c] * inv;
    const float var  = g_stats[L * 128 + 64 + c] * inv - mean * mean;
    a  = g[c] * rsqrtf(var + 1e-5f);
    cc = be[c] - mean * a;
}

// ============================================================================
// 3) Layer 1: gather features (2 elements/thread), packed 6->32 conv, z1, stats.
// ============================================================================
__global__ void __launch_bounds__(256) l1_kernel(const float* __restrict__ xyz,
                                                 const float* __restrict__ pts,
                                                 const float* __restrict__ w,
                                                 const float* __restrict__ bias,
                                                 const float* __restrict__ newxyz)
{
    __shared__ ull   swd[192];
    __shared__ ull   sb2[32];
    __shared__ float ssum[32], ssq[32];
    const int tid = threadIdx.x, lane = tid & 31;
    if (tid < 192) { float v = w[tid]; swd[tid] = pack2(v, v); }
    if (tid < 32)  { float v = bias[tid]; sb2[tid] = pack2(v, v); ssum[tid] = 0.f; ssq[tid] = 0.f; }
    __syncthreads();

    const int gt = blockIdx.x * 256 + tid;        // pair id < CNT/2
    const int e0 = 2 * gt;
    const int bs = e0 >> 5;
    const int b  = bs >> 11;
    const int2 pp = *(const int2*)&g_ball[e0];
    const float* xb = xyz + (size_t)b * NN * 3;
    const float* pb = pts + (size_t)b * NN * 3;
    const float nx = newxyz[(size_t)bs * 3 + 0];
    const float ny = newxyz[(size_t)bs * 3 + 1];
    const float nz = newxyz[(size_t)bs * 3 + 2];

    ull in2[6];
    in2[0] = pack2(xb[3 * pp.x + 0] - nx, xb[3 * pp.y + 0] - nx);
    in2[1] = pack2(xb[3 * pp.x + 1] - ny, xb[3 * pp.y + 1] - ny);
    in2[2] = pack2(xb[3 * pp.x + 2] - nz, xb[3 * pp.y + 2] - nz);
    in2[3] = pack2(pb[3 * pp.x + 0], pb[3 * pp.y + 0]);
    in2[4] = pack2(pb[3 * pp.x + 1], pb[3 * pp.y + 1]);
    in2[5] = pack2(pb[3 * pp.x + 2], pb[3 * pp.y + 2]);

#pragma unroll 4
    for (int o = 0; o < 32; o++) {
        ull acc = sb2[o];
#pragma unroll
        for (int i = 0; i < 6; i++) acc = fma2(swd[o * 6 + i], in2[i], acc);
        *(ull*)&g_bufA[(size_t)o * CNT + e0] = acc;     // STG.64, coalesced
        float lo, hi; unpack2(acc, lo, hi);
        warp_stat_accum2(lo + hi, fmaf(hi, hi, lo * lo), o, lane, ssum, ssq);
    }
    __syncthreads();
    if (tid < 32) {
        atomicAdd(&g_stats[0 * 128 + tid],      ssum[tid]);
        atomicAdd(&g_stats[0 * 128 + 64 + tid], ssq[tid]);
    }
}

// ============================================================================
// 4) Layer 2: BN1+relu on z1 (affine computed inline from stats), packed
//    32->32 conv (2 elements/thread), z2, stats.
// ============================================================================
__global__ void __launch_bounds__(256) l2_kernel(const float* __restrict__ w,
                                                 const float* __restrict__ bias,
                                                 const float* __restrict__ g0,
                                                 const float* __restrict__ be0)
{
    __shared__ ull   swd[1024];
    __shared__ ull   sb2[32], sa2[32], sc2[32];
    __shared__ float ssum[32], ssq[32];
    const int tid = threadIdx.x, lane = tid & 31;
    for (int i = tid; i < 1024; i += 256) { float v = w[i]; swd[i] = pack2(v, v); }
    if (tid < 32) {
        float v = bias[tid]; sb2[tid] = pack2(v, v);
        float a, c; bn_affine(0, tid, g0, be0, a, c);
        sa2[tid] = pack2(a, a); sc2[tid] = pack2(c, c);
        ssum[tid] = 0.f; ssq[tid] = 0.f;
    }
    __syncthreads();

    const int e0 = 2 * (blockIdx.x * 256 + tid);
    ull h2[32];
#pragma unroll
    for (int i = 0; i < 32; i++) {
        ull z = *(const ull*)&g_bufA[(size_t)i * CNT + e0];
        ull t = fma2(sa2[i], z, sc2[i]);
        float lo, hi; unpack2(t, lo, hi);
        h2[i] = pack2(fmaxf(lo, 0.f), fmaxf(hi, 0.f));
    }
#pragma unroll 2
    for (int o = 0; o < 32; o++) {
        ull acc = sb2[o];
#pragma unroll
        for (int i = 0; i < 32; i++) acc = fma2(swd[o * 32 + i], h2[i], acc);
        *(ull*)&g_bufB[(size_t)o * CNT + e0] = acc;
        float lo, hi; unpack2(acc, lo, hi);
        warp_stat_accum2(lo + hi, fmaf(hi, hi, lo * lo), o, lane, ssum, ssq);
    }
    __syncthreads();
    if (tid < 32) {
        atomicAdd(&g_stats[1 * 128 + tid],      ssum[tid]);
        atomicAdd(&g_stats[1 * 128 + 64 + tid], ssq[tid]);
    }
}

// ============================================================================
// 5) Layer 3: BN2+relu on z2 (affine inline), packed 32->64 conv, stats, and
//    FUSED max over k: z3 never hits DRAM (bit-exact: a3>0, monotone fmaf/relu).
// ============================================================================
__global__ void __launch_bounds__(256) l3_kernel(const float* __restrict__ w,
                                                 const float* __restrict__ bias,
                                                 const float* __restrict__ g1,
                                                 const float* __restrict__ be1)
{
    __shared__ ull   swd[2048];       // 16KB
    __shared__ ull   sb2[64], sa2[32], sc2[32];
    __shared__ float ssum[64], ssq[64];
    __shared__ float smax[16][64];    // 16 bs-groups per block
    const int tid = threadIdx.x, lane = tid & 31, warp = tid >> 5;
    for (int i = tid; i < 2048; i += 256) { float v = w[i]; swd[i] = pack2(v, v); }
    if (tid < 64) { float v = bias[tid]; sb2[tid] = pack2(v, v); ssum[tid] = 0.f; ssq[tid] = 0.f; }
    if (tid < 32) {
        float a, c; bn_affine(1, tid, g1, be1, a, c);
        sa2[tid] = pack2(a, a); sc2[tid] = pack2(c, c);
    }
    __syncthreads();

    const int e0 = 2 * (blockIdx.x * 256 + tid);
    ull h2[32];
#pragma unroll
    for (int i = 0; i < 32; i++) {
        ull z = *(const ull*)&g_bufB[(size_t)i * CNT + e0];
        ull t = fma2(sa2[i], z, sc2[i]);
        float lo, hi; unpack2(t, lo, hi);
        h2[i] = pack2(fmaxf(lo, 0.f), fmaxf(hi, 0.f));
    }
    const int seg = (warp << 1) + (lane >> 4);    // bs-group within block (0..15)
#pragma unroll 1
    for (int o = 0; o < 64; o++) {
        ull acc = sb2[o];
#pragma unroll
        for (int i = 0; i < 32; i++) acc = fma2(swd[o * 32 + i], h2[i], acc);
        float lo, hi; unpack2(acc, lo, hi);
        float mx = fmaxf(lo, hi);
#pragma unroll
        for (int off = 8; off > 0; off >>= 1)
            mx = fmaxf(mx, __shfl_down_sync(0xffffffffu, mx, off, 16));
        if ((lane & 15) == 0) smax[seg][o] = mx;
        warp_stat_accum2(lo + hi, fmaf(hi, hi, lo * lo), o, lane, ssum, ssq);
    }
    __syncthreads();
    {
        const int bs0 = blockIdx.x * 16;
        for (int i = tid; i < 16 * 64; i += 256)
            g_max[(size_t)bs0 * 64 + i] = smax[i >> 6][i & 63];
    }
    if (tid < 64) {
        atomicAdd(&g_stats[2 * 128 + tid],      ssum[tid]);
        atomicAdd(&g_stats[2 * 128 + 64 + tid], ssq[tid]);
    }
}

// ============================================================================
// 6) Finalize: BN3 affine (inline from stats) + relu on the per-(bs,o) maxima.
// ============================================================================
__global__ void __launch_bounds__(256) final_kernel(const float* __restrict__ g2,
                                                    const float* __restrict__ be2,
                                                    float* __restrict__ out)
{
    __shared__ float sa[64], sc[64];
    const int tid = threadIdx.x;
    if (tid < 64) {
        float a, c; bn_affine(2, tid, g2, be2, a, c);
        sa[tid] = a; sc[tid] = c;
    }
    __syncthreads();

    const int idx = blockIdx.x * 256 + tid;       // < BB*SS*64
    const int o = idx & 63;
    const float v = g_max[idx];
    out[OUT_XYZ_ELEMS + idx] = fmaxf(fmaf(sa[o], v, sc[o]), 0.f);
}

// ============================================================================
extern "C" void kernel_launch(void* const* d_in, const int* in_sizes, int n_in,
                              void* d_out, int out_size)
{
    const float* xyz = (const float*)d_in[0];
    const float* pts = (const float*)d_in[1];
    const float* w0  = (const float*)d_in[2];
    const float* b0  = (const float*)d_in[3];
    const float* g0  = (const float*)d_in[4];
    const float* be0 = (const float*)d_in[5];
    const float* w1  = (const float*)d_in[6];
    const float* b1  = (const float*)d_in[7];
    const float* g1  = (const float*)d_in[8];
    const float* be1 = (const float*)d_in[9];
    const float* w2  = (const float*)d_in[10];
    const float* b2  = (const float*)d_in[11];
    const float* g2  = (const float*)d_in[12];
    const float* be2 = (const float*)d_in[13];
    float* out = (float*)d_out;

    fps_kernel<<<BB, 512>>>(xyz);
    bq_kernel<<<(BB * SS) / 8, 256>>>(xyz, out);
    l1_kernel<<<CNT / 512, 256>>>(xyz, pts, w0, b0, out);
    l2_kernel<<<CNT / 512, 256>>>(w1, b1, g0, be0);
    l3_kernel<<<CNT / 512, 256>>>(w2, b2, g1, be1);
    final_kernel<<<(BB * SS * 64) / 256, 256>>>(g2, be2, out);
}

// round 13
// speedup vs baseline: 1.1366x; 1.0666x over previous
#include <cuda_runtime.h>
#include <math.h>

#define BB 8
#define NN 8192
#define SS 2048
#define KK 32
#define CNT (BB*SS*KK)          // 524288 elements per layer
#define OUT_XYZ_ELEMS (BB*SS*3) // 49152

typedef unsigned long long ull;

// ---------------- scratch (static device memory; no runtime allocation) ----
__device__ float g_bufA[(size_t)CNT * 32];  // 64 MB : z1 (32ch), channel-major [c][e]
__device__ float g_bufB[(size_t)CNT * 32];  // 64 MB : z2 (32ch), channel-major
__device__ float g_max[(size_t)BB * SS * 64]; // 4 MB : per-(b,s) max_k z3, [bs][o]
__device__ int   g_fps[BB * SS];
__device__ int   g_ball[BB * SS * KK];
__device__ float g_stats[3 * 128];          // per layer: [0..63]=sum, [64..127]=sumsq

// ---------------- packed f32x2 helpers (sm_103a) ---------------------------
__device__ __forceinline__ ull pack2(float lo, float hi) {
    ull r; asm("mov.b64 %0,{%1,%2};" : "=l"(r) : "f"(lo), "f"(hi)); return r;
}
__device__ __forceinline__ void unpack2(ull v, float& lo, float& hi) {
    asm("mov.b64 {%0,%1},%2;" : "=f"(lo), "=f"(hi) : "l"(v));
}
__device__ __forceinline__ ull add2(ull a, ull b) {
    ull r; asm("add.rn.f32x2 %0,%1,%2;" : "=l"(r) : "l"(a), "l"(b)); return r;
}
__device__ __forceinline__ ull mul2(ull a, ull b) {
    ull r; asm("mul.rn.f32x2 %0,%1,%2;" : "=l"(r) : "l"(a), "l"(b)); return r;
}
__device__ __forceinline__ ull fma2(ull a, ull b, ull c) {
    ull r; asm("fma.rn.f32x2 %0,%1,%2,%3;" : "=l"(r) : "l"(a), "l"(b), "l"(c)); return r;
}

// ============================================================================
// 1) Farthest point sampling (UNCHANGED from the 1358us-passing structure).
// ============================================================================
__global__ void __launch_bounds__(512) fps_kernel(const float* __restrict__ xyz)
{
    const int b = blockIdx.x;
    const float* base = xyz + (size_t)b * NN * 3;
    const int t = threadIdx.x;
    const int lane = t & 31, wid = t >> 5;

    ull px[8], py[8], pz[8];
    float dd[16];
#pragma unroll
    for (int k = 0; k < 8; k++) {
        const int p0 = t + (2 * k) * 512;
        const int p1 = t + (2 * k + 1) * 512;
        px[k] = pack2(base[3 * p0 + 0], base[3 * p1 + 0]);
        py[k] = pack2(base[3 * p0 + 1], base[3 * p1 + 1]);
        pz[k] = pack2(base[3 * p0 + 2], base[3 * p1 + 2]);
    }
#pragma unroll
    for (int j = 0; j < 16; j++) dd[j] = 1e10f;

    __shared__ unsigned sdist[16];
    __shared__ unsigned sidxs[3];
    if (t < 3) sidxs[t] = 0xffffffffu;
    __syncthreads();

    float cx = base[0], cy = base[1], cz = base[2];
    int cur = 0;
    int slot = 0, nslot = 1, rslot = 2;

    for (int it = 0; it < SS; it++) {
        if (t == 0) {
            g_fps[b * SS + it] = cur;
            sidxs[nslot] = 0xffffffffu;
        }
        const ull ncx = pack2(-cx, -cx);
        const ull ncy = pack2(-cy, -cy);
        const ull ncz = pack2(-cz, -cz);

        float m0 = 0.f, m1 = 0.f;
#pragma unroll
        for (int k = 0; k < 8; k++) {
            ull dx = add2(px[k], ncx);
            ull dy = add2(py[k], ncy);
            ull dz = add2(pz[k], ncz);
            ull d2 = mul2(dx, dx);
            d2 = fma2(dy, dy, d2);
            d2 = fma2(dz, dz, d2);
            float dlo, dhi; unpack2(d2, dlo, dhi);
            const float nlo = fminf(dd[2 * k],     dlo);
            const float nhi = fminf(dd[2 * k + 1], dhi);
            dd[2 * k]     = nlo;
            dd[2 * k + 1] = nhi;
            m0 = fmaxf(m0, nlo);
            m1 = fmaxf(m1, nhi);
        }
        const float m = fmaxf(m0, m1);
        const unsigned mb   = __float_as_uint(m);
        const unsigned wmax = __reduce_max_sync(0xffffffffu, mb);
        if (lane == 0) sdist[wid] = wmax;
        __syncthreads();

        const unsigned bmax = __reduce_max_sync(0xffffffffu, sdist[lane & 15]);

        if (wmax == bmax) {
            unsigned bi = 0xffffffffu;
            if (mb == bmax) {
#pragma unroll
                for (int j = 15; j >= 0; j--)
                    if (__float_as_uint(dd[j]) == bmax) bi = (unsigned)(t + j * 512);
            }
            const unsigned rid = __reduce_min_sync(0xffffffffu, bi);
            if (lane == 0) atomicMin(&sidxs[slot], rid);
        }
        __syncthreads();

        cur = (int)sidxs[slot];
        cx = base[3 * cur + 0];
        cy = base[3 * cur + 1];
        cz = base[3 * cur + 2];

        const int tmp = slot; slot = nslot; nslot = rslot; rslot = tmp;
    }
}

// ============================================================================
// 2) new_xyz gather + ball query (UNCHANGED).
// ============================================================================
#define TPTS 1024
__global__ void __launch_bounds__(256) bq_kernel(const float* __restrict__ xyz,
                                                 float* __restrict__ newxyz)
{
    const int tid = threadIdx.x;
    if (blockIdx.x == 0) {
        for (int i = tid; i < 384; i += 256) g_stats[i] = 0.f;
    }

    const int warp = tid >> 5, lane = tid & 31;
    const int gs = blockIdx.x * 8 + warp;
    const int b  = gs >> 11;
    const float* base = xyz + (size_t)b * NN * 3;

    __shared__ float spts[TPTS * 3];
    __shared__ int   sidx[8][KK];
    __shared__ int   sdone;
    if (tid == 0) sdone = 0;

    const int ci = g_fps[gs];
    const float cx = base[3 * ci + 0];
    const float cy = base[3 * ci + 1];
    const float cz = base[3 * ci + 2];
    if (lane < 3) newxyz[(size_t)gs * 3 + lane] = base[3 * ci + lane];

    const float r2 = (float)(0.2 * 0.2);
    int cnt = 0, first = 0x7fffffff;
    bool done = false;

    for (int tile = 0; tile < NN; tile += TPTS) {
        __syncthreads();
        if (sdone == 8) break;
        for (int i = tid; i < TPTS * 3; i += 256)
            spts[i] = base[(size_t)tile * 3 + i];
        __syncthreads();

        if (!done) {
            for (int p0 = 0; p0 < TPTS; p0 += 32) {
                const int p = p0 + lane;
                float dx = spts[3 * p + 0] - cx;
                float dy = spts[3 * p + 1] - cy;
                float dz = spts[3 * p + 2] - cz;
                float sq = dx * dx + dy * dy + dz * dz;
                bool  in = !(sq > r2);
                unsigned mm = __ballot_sync(0xffffffffu, in);
                if (in) {
                    int pos = cnt + __popc(mm & ((1u << lane) - 1u));
                    if (pos < KK) sidx[warp][pos] = tile + p;
                    if (pos == 0) first = tile + p;
                }
                cnt += __popc(mm);
                if (cnt >= KK) break;
            }
            if (cnt >= KK) {
                done = true;
                if (lane == 0) atomicAdd(&sdone, 1);
            }
        }
    }
#pragma unroll
    for (int off = 16; off > 0; off >>= 1)
        first = min(first, __shfl_down_sync(0xffffffffu, first, off));
    first = __shfl_sync(0xffffffffu, first, 0);

    const int cc = cnt < KK ? cnt : KK;
    const int v  = (lane < cc) ? sidx[warp][lane] : first;
    g_ball[(size_t)gs * KK + lane] = v;
}

// BN affine from stats
__device__ __forceinline__ void bn_affine(int L, int c,
                                          const float* __restrict__ g,
                                          const float* __restrict__ be,
                                          float& a, float& cc)
{
    const float inv  = 1.f / (float)CNT;
    const float mean = g_stats[L * 128 + c] * inv;
    const float var  = g_stats[L * 128 + 64 + c] * inv - mean * mean;
    a  = g[c] * rsqrtf(var + 1e-5f);
    cc = be[c] - mean * a;
}

// ============================================================================
// 3) Layer 1 REDESIGNED: block = 256 elements (128 pairs). Gather features to
//    smem h[6][128]; warp w owns channels {w,w+8,w+16,w+24}; lane owns 4 pairs.
//    Weight regs reused over 4 pairs -> fewer LDS; stats per channel have a
//    single warp owner (one shuffle reduce, single-writer smem, no atomics).
// ============================================================================
__global__ void __launch_bounds__(256) l1_kernel(const float* __restrict__ xyz,
                                                 const float* __restrict__ pts,
                                                 const float* __restrict__ w,
                                                 const float* __restrict__ bias,
                                                 const float* __restrict__ newxyz)
{
    __shared__ ull   hsm[6][128];
    __shared__ ull   swd2[192];
    __shared__ ull   sb2[32];
    __shared__ float ssum[32], ssq[32];
    const int tid = threadIdx.x;
    if (tid < 192) { float v = w[tid]; swd2[tid] = pack2(v, v); }
    if (tid < 32)  { float v = bias[tid]; sb2[tid] = pack2(v, v); }
    __syncthreads();

    const int P0 = blockIdx.x * 128;              // pair base
    if (tid < 128) {                              // gather one pair per thread
        const int e0 = 2 * (P0 + tid);
        const int bs = e0 >> 5;
        const int b  = bs >> 11;
        const int2 pp = *(const int2*)&g_ball[e0];
        const float* xb = xyz + (size_t)b * NN * 3;
        const float* pb = pts + (size_t)b * NN * 3;
        const float nx = newxyz[(size_t)bs * 3 + 0];
        const float ny = newxyz[(size_t)bs * 3 + 1];
        const float nz = newxyz[(size_t)bs * 3 + 2];
        hsm[0][tid] = pack2(xb[3 * pp.x + 0] - nx, xb[3 * pp.y + 0] - nx);
        hsm[1][tid] = pack2(xb[3 * pp.x + 1] - ny, xb[3 * pp.y + 1] - ny);
        hsm[2][tid] = pack2(xb[3 * pp.x + 2] - nz, xb[3 * pp.y + 2] - nz);
        hsm[3][tid] = pack2(pb[3 * pp.x + 0], pb[3 * pp.y + 0]);
        hsm[4][tid] = pack2(pb[3 * pp.x + 1], pb[3 * pp.y + 1]);
        hsm[5][tid] = pack2(pb[3 * pp.x + 2], pb[3 * pp.y + 2]);
    }
    __syncthreads();

    const int wp = tid >> 5, l = tid & 31;
    ull acc[4][4];
#pragma unroll
    for (int j = 0; j < 4; j++) {
        const ull bj = sb2[wp + 8 * j];
#pragma unroll
        for (int q = 0; q < 4; q++) acc[j][q] = bj;
    }
#pragma unroll
    for (int i = 0; i < 6; i++) {
        ull wv[4], hv[4];
#pragma unroll
        for (int j = 0; j < 4; j++) wv[j] = swd2[(wp + 8 * j) * 6 + i];
#pragma unroll
        for (int q = 0; q < 4; q++) hv[q] = hsm[i][l + 32 * q];
#pragma unroll
        for (int j = 0; j < 4; j++)
#pragma unroll
            for (int q = 0; q < 4; q++)
                acc[j][q] = fma2(wv[j], hv[q], acc[j][q]);
    }
#pragma unroll
    for (int j = 0; j < 4; j++) {
        const int c = wp + 8 * j;
        float v = 0.f, v2 = 0.f;
#pragma unroll
        for (int q = 0; q < 4; q++) {
            const int e = 2 * (P0 + l + 32 * q);
            *(ull*)&g_bufA[(size_t)c * CNT + e] = acc[j][q];   // coalesced STG.64
            float lo, hi; unpack2(acc[j][q], lo, hi);
            v  += lo + hi;
            v2 += fmaf(hi, hi, lo * lo);
        }
#pragma unroll
        for (int off = 16; off > 0; off >>= 1) {
            v  += __shfl_down_sync(0xffffffffu, v,  off);
            v2 += __shfl_down_sync(0xffffffffu, v2, off);
        }
        if (l == 0) { ssum[c] = v; ssq[c] = v2; }   // single writer per channel
    }
    __syncthreads();
    if (tid < 32) {
        atomicAdd(&g_stats[0 * 128 + tid],      ssum[tid]);
        atomicAdd(&g_stats[0 * 128 + 64 + tid], ssq[tid]);
    }
}

// ============================================================================
// 4) Layer 2 REDESIGNED: stage relu(affine(z1)) tile h[32][128] in smem, then
//    warp-per-channel-group GEMM: 8 LDS per 16 fma2 (weights+h reused).
// ============================================================================
__global__ void __launch_bounds__(256) l2_kernel(const float* __restrict__ w,
                                                 const float* __restrict__ bias,
                                                 const float* __restrict__ g0,
                                                 const float* __restrict__ be0)
{
    __shared__ ull   hsm[32][128];     // 32 KB
    __shared__ ull   swd2[1024];       // 8 KB
    __shared__ ull   sb2[32], sa2[32], sc2[32];
    __shared__ float ssum[32], ssq[32];
    const int tid = threadIdx.x;
    for (int i = tid; i < 1024; i += 256) { float v = w[i]; swd2[i] = pack2(v, v); }
    if (tid < 32) {
        float v = bias[tid]; sb2[tid] = pack2(v, v);
        float a, c; bn_affine(0, tid, g0, be0, a, c);
        sa2[tid] = pack2(a, a); sc2[tid] = pack2(c, c);
    }
    __syncthreads();

    const int P0 = blockIdx.x * 128;
    {   // stage: each thread covers 16 input channels of one pair
        const int pr = tid & 127, half = tid >> 7;
        const int e0 = 2 * (P0 + pr);
#pragma unroll
        for (int k = 0; k < 16; k++) {
            const int i = half * 16 + k;
            ull z = *(const ull*)&g_bufA[(size_t)i * CNT + e0];   // LDG.64 coalesced
            ull t = fma2(sa2[i], z, sc2[i]);
            float lo, hi; unpack2(t, lo, hi);
            hsm[i][pr] = pack2(fmaxf(lo, 0.f), fmaxf(hi, 0.f));
        }
    }
    __syncthreads();

    const int wp = tid >> 5, l = tid & 31;
    ull acc[4][4];
#pragma unroll
    for (int j = 0; j < 4; j++) {
        const ull bj = sb2[wp + 8 * j];
#pragma unroll
        for (int q = 0; q < 4; q++) acc[j][q] = bj;
    }
#pragma unroll 4
    for (int i = 0; i < 32; i++) {
        ull wv[4], hv[4];
#pragma unroll
        for (int j = 0; j < 4; j++) wv[j] = swd2[(wp + 8 * j) * 32 + i];  // broadcast LDS
#pragma unroll
        for (int q = 0; q < 4; q++) hv[q] = hsm[i][l + 32 * q];           // conflict-free
#pragma unroll
        for (int j = 0; j < 4; j++)
#pragma unroll
            for (int q = 0; q < 4; q++)
                acc[j][q] = fma2(wv[j], hv[q], acc[j][q]);
    }
#pragma unroll
    for (int j = 0; j < 4; j++) {
        const int c = wp + 8 * j;
        float v = 0.f, v2 = 0.f;
#pragma unroll
        for (int q = 0; q < 4; q++) {
            const int e = 2 * (P0 + l + 32 * q);
            *(ull*)&g_bufB[(size_t)c * CNT + e] = acc[j][q];
            float lo, hi; unpack2(acc[j][q], lo, hi);
            v  += lo + hi;
            v2 += fmaf(hi, hi, lo * lo);
        }
#pragma unroll
        for (int off = 16; off > 0; off >>= 1) {
            v  += __shfl_down_sync(0xffffffffu, v,  off);
            v2 += __shfl_down_sync(0xffffffffu, v2, off);
        }
        if (l == 0) { ssum[c] = v; ssq[c] = v2; }
    }
    __syncthreads();
    if (tid < 32) {
        atomicAdd(&g_stats[1 * 128 + tid],      ssum[tid]);
        atomicAdd(&g_stats[1 * 128 + 64 + tid], ssq[tid]);
    }
}

// ============================================================================
// 5) Layer 3 REDESIGNED: same pattern, 64 output channels (8 per warp), with
//    the bit-exact fused k-max (a 16-lane x fixed-q segment = one bs of 16
//    consecutive pairs). Dynamic smem (52.7KB).
// ============================================================================
#define SMEM_L3 (32*128*8 + 2048*8 + 64*8 + 32*8 + 32*8 + 64*4 + 64*4 + 8*64*4)
__global__ void __launch_bounds__(256) l3_kernel(const float* __restrict__ w,
                                                 const float* __restrict__ bias,
                                                 const float* __restrict__ g1,
                                                 const float* __restrict__ be1)
{
    extern __shared__ char smraw[];
    ull*   hsm  = (ull*)smraw;            // [32][128]
    ull*   swd2 = hsm + 32 * 128;         // [2048]
    ull*   sb2  = swd2 + 2048;            // [64]
    ull*   sa2  = sb2 + 64;               // [32]
    ull*   sc2  = sa2 + 32;               // [32]
    float* ssum = (float*)(sc2 + 32);     // [64]
    float* ssq  = ssum + 64;              // [64]
    float* smax = ssq + 64;               // [8][64]

    const int tid = threadIdx.x;
    for (int i = tid; i < 2048; i += 256) { float v = w[i]; swd2[i] = pack2(v, v); }
    if (tid < 64) { float v = bias[tid]; sb2[tid] = pack2(v, v); }
    if (tid < 32) {
        float a, c; bn_affine(1, tid, g1, be1, a, c);
        sa2[tid] = pack2(a, a); sc2[tid] = pack2(c, c);
    }
    __syncthreads();

    const int P0 = blockIdx.x * 128;
    {
        const int pr = tid & 127, half = tid >> 7;
        const int e0 = 2 * (P0 + pr);
#pragma unroll
        for (int k = 0; k < 16; k++) {
            const int i = half * 16 + k;
            ull z = *(const ull*)&g_bufB[(size_t)i * CNT + e0];
            ull t = fma2(sa2[i], z, sc2[i]);
            float lo, hi; unpack2(t, lo, hi);
            hsm[i * 128 + pr] = pack2(fmaxf(lo, 0.f), fmaxf(hi, 0.f));
        }
    }
    __syncthreads();

    const int wp = tid >> 5, l = tid & 31;
    ull acc[8][4];
#pragma unroll
    for (int j = 0; j < 8; j++) {
        const ull bj = sb2[wp + 8 * j];
#pragma unroll
        for (int q = 0; q < 4; q++) acc[j][q] = bj;
    }
#pragma unroll 2
    for (int i = 0; i < 32; i++) {
        ull wv[8], hv[4];
#pragma unroll
        for (int j = 0; j < 8; j++) wv[j] = swd2[(wp + 8 * j) * 32 + i];
#pragma unroll
        for (int q = 0; q < 4; q++) hv[q] = hsm[i * 128 + l + 32 * q];
#pragma unroll
        for (int j = 0; j < 8; j++)
#pragma unroll
            for (int q = 0; q < 4; q++)
                acc[j][q] = fma2(wv[j], hv[q], acc[j][q]);
    }
#pragma unroll
    for (int j = 0; j < 8; j++) {
        const int c = wp + 8 * j;
        float v = 0.f, v2 = 0.f;
#pragma unroll
        for (int q = 0; q < 4; q++) {
            float lo, hi; unpack2(acc[j][q], lo, hi);
            v  += lo + hi;
            v2 += fmaf(hi, hi, lo * lo);
            // fused max over the bs segment (16 consecutive pairs)
            float mx = fmaxf(lo, hi);
#pragma unroll
            for (int off = 8; off > 0; off >>= 1)
                mx = fmaxf(mx, __shfl_down_sync(0xffffffffu, mx, off, 16));
            if ((l & 15) == 0) smax[(2 * q + (l >> 4)) * 64 + c] = mx;
        }
#pragma unroll
        for (int off = 16; off > 0; off >>= 1) {
            v  += __shfl_down_sync(0xffffffffu, v,  off);
            v2 += __shfl_down_sync(0xffffffffu, v2, off);
        }
        if (l == 0) { ssum[c] = v; ssq[c] = v2; }
    }
    __syncthreads();
    for (int idx = tid; idx < 512; idx += 256)        // 8 bs x 64 ch, coalesced
        g_max[(size_t)blockIdx.x * 512 + idx] = smax[idx];
    if (tid < 64) {
        atomicAdd(&g_stats[2 * 128 + tid],      ssum[tid]);
        atomicAdd(&g_stats[2 * 128 + 64 + tid], ssq[tid]);
    }
}

// ============================================================================
// 6) Finalize: BN3 affine (inline from stats) + relu on the per-(bs,o) maxima.
// ============================================================================
__global__ void __launch_bounds__(256) final_kernel(const float* __restrict__ g2,
                                                    const float* __restrict__ be2,
                                                    float* __restrict__ out)
{
    __shared__ float sa[64], sc[64];
    const int tid = threadIdx.x;
    if (tid < 64) {
        float a, c; bn_affine(2, tid, g2, be2, a, c);
        sa[tid] = a; sc[tid] = c;
    }
    __syncthreads();

    const int idx = blockIdx.x * 256 + tid;
    const int o = idx & 63;
    const float v = g_max[idx];
    out[OUT_XYZ_ELEMS + idx] = fmaxf(fmaf(sa[o], v, sc[o]), 0.f);
}

// ============================================================================
extern "C" void kernel_launch(void* const* d_in, const int* in_sizes, int n_in,
                              void* d_out, int out_size)
{
    const float* xyz = (const float*)d_in[0];
    const float* pts = (const float*)d_in[1];
    const float* w0  = (const float*)d_in[2];
    const float* b0  = (const float*)d_in[3];
    const float* g0  = (const float*)d_in[4];
    const float* be0 = (const float*)d_in[5];
    const float* w1  = (const float*)d_in[6];
    const float* b1  = (const float*)d_in[7];
    const float* g1  = (const float*)d_in[8];
    const float* be1 = (const float*)d_in[9];
    const float* w2  = (const float*)d_in[10];
    const float* b2  = (const float*)d_in[11];
    const float* g2  = (const float*)d_in[12];
    const float* be2 = (const float*)d_in[13];
    float* out = (float*)d_out;

    cudaFuncSetAttribute(l3_kernel,
                         cudaFuncAttributeMaxDynamicSharedMemorySize, SMEM_L3);

    fps_kernel<<<BB, 512>>>(xyz);
    bq_kernel<<<(BB * SS) / 8, 256>>>(xyz, out);
    l1_kernel<<<CNT / 256, 256>>>(xyz, pts, w0, b0, out);
    l2_kernel<<<CNT / 256, 256>>>(w1, b1, g0, be0);
    l3_kernel<<<CNT / 256, 256, SMEM_L3>>>(w2, b2, g1, be1);
    final_kernel<<<(BB * SS * 64) / 256, 256>>>(g2, be2, out);
}